// round 5
// baseline (speedup 1.0000x reference)
#include <cuda_runtime.h>
#include <cuda_bf16.h>
#include <stdint.h>

// ---------------------------------------------------------------------------
// WaffleIron block on GB300.
// Shapes: B=2, C=256, N=32768, D=4, H=W=256, HW=65536, NG=3.
// Internal token layout: [B*N, C] (C contiguous) for coalesced everything.
// GEMMs in bf16 mma.sync (m16n8k16). Depthwise convs fused (conv1+ReLU+conv2).
// Grids stored in bf16 (halves grid HBM traffic; scatter uses bf16x2 atomics).
// Channel-BN stats fused into gather; spatial-BN stats fused into gemm2
// epilogue (standalone stats pass only for layer 0).
// ---------------------------------------------------------------------------

#define Bn   2
#define Cc   256
#define Nn   32768
#define Dd   4
#define Hh   256
#define Ww   256
#define HW   65536
#define NG   3
#define ROWS (Bn * Nn)          // 65536 token rows

// ---------------- scratch (static device memory; no allocs) ----------------
__device__ float          g_tokensT[(size_t)ROWS * Cc];        // 67 MB
__device__ __nv_bfloat16  g_grid  [(size_t)Bn * HW * Cc];      // 67 MB (scatter dst)
__device__ __nv_bfloat16  g_grid2 [(size_t)Bn * HW * Cc];      // 67 MB (conv out)
__device__ __nv_bfloat16  g_H1    [(size_t)ROWS * Cc];         // 33.5 MB
__device__ float          g_counts[Bn * NG * HW];              // 1.5 MB
__device__ float          g_acc   [2 * Cc];
__device__ float          g_bnA   [Cc];
__device__ float          g_bnB   [Cc];

// ---------------- small utility kernels ----------------
__global__ void zero4_kernel(float4* p, int n4) {
    int i = blockIdx.x * blockDim.x + threadIdx.x;
    if (i < n4) p[i] = make_float4(0.f, 0.f, 0.f, 0.f);
}

__global__ void hist_kernel(const int* __restrict__ cellind,
                            const float* __restrict__ occ) {
    int idx = blockIdx.x * 256 + threadIdx.x;      // < B*NG*N
    int b   = idx / (NG * Nn);
    int n   = idx % Nn;
    int bg  = idx / Nn;                            // b*NG + g
    atomicAdd(&g_counts[bg * HW + cellind[idx]], occ[b * Nn + n]);
}

// [B,C,N] -> tokensT [B*N, C]
__global__ void transpose_in_kernel(const float* __restrict__ src) {
    __shared__ float tile[32][33];
    int b  = blockIdx.z;
    int n0 = blockIdx.x * 32, c0 = blockIdx.y * 32;
    int tx = threadIdx.x, ty = threadIdx.y;
#pragma unroll
    for (int j = 0; j < 32; j += 8)
        tile[ty + j][tx] = src[((size_t)b * Cc + c0 + ty + j) * Nn + n0 + tx];
    __syncthreads();
#pragma unroll
    for (int j = 0; j < 32; j += 8)
        g_tokensT[((size_t)b * Nn + n0 + ty + j) * Cc + c0 + tx] = tile[tx][ty + j];
}

// tokensT -> d_out [B,C,N]
__global__ void transpose_out_kernel(float* __restrict__ dst) {
    __shared__ float tile[32][33];
    int b  = blockIdx.z;
    int n0 = blockIdx.x * 32, c0 = blockIdx.y * 32;
    int tx = threadIdx.x, ty = threadIdx.y;
#pragma unroll
    for (int j = 0; j < 32; j += 8)
        tile[ty + j][tx] = g_tokensT[((size_t)b * Nn + n0 + ty + j) * Cc + c0 + tx];
    __syncthreads();
#pragma unroll
    for (int j = 0; j < 32; j += 8)
        dst[((size_t)b * Cc + c0 + ty + j) * Nn + n0 + tx] = tile[tx][ty + j];
}

// ---------------- BatchNorm stats (standalone; layer-0 spatial only) -------
__global__ void bn_accum_kernel() {
    int c  = threadIdx.x;
    int r0 = blockIdx.x * 256;
    float s = 0.f, s2 = 0.f;
    for (int r = 0; r < 256; r++) {
        float x = g_tokensT[(size_t)(r0 + r) * Cc + c];
        s += x; s2 += x * x;
    }
    atomicAdd(&g_acc[c], s);
    atomicAdd(&g_acc[Cc + c], s2);
}

__global__ void bn_final_kernel(const float* __restrict__ gamma,
                                const float* __restrict__ beta) {
    int c = threadIdx.x;
    const float inv = 1.f / (float)ROWS;
    float m = g_acc[c] * inv;
    float v = g_acc[Cc + c] * inv - m * m;
    float a = rsqrtf(v + 1e-5f) * __ldg(&gamma[c]);
    g_bnA[c] = a;
    g_bnB[c] = __ldg(&beta[c]) - m * a;
}

// ---------------- scatter (BN fused, bf16x2 atomics) ----------------
// 128 threads = 128 channel pairs; 4 points per block.
__global__ void scatter_kernel(const int* __restrict__ cellind,
                               const float* __restrict__ occ, int g) {
    const int c = threadIdx.x * 2;            // even channel of the pair
    const float a0 = g_bnA[c], a1 = g_bnA[c + 1];
    const float b0 = g_bnB[c], b1 = g_bnB[c + 1];
#pragma unroll
    for (int i = 0; i < 4; i++) {
        int p = blockIdx.x * 4 + i;           // 0..ROWS-1
        int b = p >> 15;                      // /Nn
        int n = p & (Nn - 1);
        int cell = __ldg(&cellind[(b * NG + g) * Nn + n]);
        float o  = __ldg(&occ[b * Nn + n]);
        float cnt = g_counts[(b * NG + g) * HW + cell];
        float w   = o / (cnt * o + 1e-6f);
        float2 x = *(const float2*)&g_tokensT[(size_t)p * Cc + c];
        __nv_bfloat162 val = __floats2bfloat162_rn((x.x * a0 + b0) * w,
                                                   (x.y * a1 + b1) * w);
        atomicAdd((__nv_bfloat162*)&g_grid[((size_t)b * HW + cell) * Cc + c], val);
    }
}

// ---------------- fused depthwise conv1 + ReLU + conv2 (bf16 I/O) ----------
// CTA: 256 threads = 8 pixel-slots x 32 channels. Output tile 8x8 pixels,
// 32 channels. Input tile 12x12 (halo 2) in smem; intermediate 10x10 in smem.
// Intermediate pixels mapping outside [0,256)^2 are forced to 0 (reference's
// second SAME conv pads conv1 *output* with zeros). Math in fp32.
#define CT 32
__global__ __launch_bounds__(256) void conv_fused_kernel(
    const __nv_bfloat16* __restrict__ in, __nv_bfloat16* __restrict__ out,
    const float* __restrict__ k1, const float* __restrict__ b1,
    const float* __restrict__ k2, const float* __restrict__ b2) {
    __shared__ float s_in [144][CT];   // 12x12
    __shared__ float s_mid[100][CT];   // 10x10
    const int c  = threadIdx.x & (CT - 1);
    const int p  = threadIdx.x >> 5;          // 0..7
    const int bz = blockIdx.z;                // b * (Cc/CT) + cchunk
    const int b  = bz >> 3;                   // Cc/CT == 8
    const int c0 = (bz & 7) * CT;
    const int x0 = blockIdx.x * 8;
    const int y0 = blockIdx.y * 8;
    const int ch = c0 + c;

    float w1[9], w2[9];
#pragma unroll
    for (int i = 0; i < 9; i++) {
        w1[i] = __ldg(&k1[ch * 9 + i]);
        w2[i] = __ldg(&k2[ch * 9 + i]);
    }
    const float bv1 = __ldg(&b1[ch]);
    const float bv2 = __ldg(&b2[ch]);

    // load 12x12 input tile (origin y0-2, x0-2), zero outside grid
    for (int t = p; t < 144; t += 8) {
        int yy = y0 - 2 + t / 12;
        int xx = x0 - 2 + t % 12;
        float v = 0.f;
        if (yy >= 0 && yy < Hh && xx >= 0 && xx < Ww)
            v = __bfloat162float(in[((size_t)b * HW + (size_t)yy * Ww + xx) * Cc + ch]);
        s_in[t][c] = v;
    }
    __syncthreads();

    // conv1 + bias + relu -> 10x10 mid tile (origin y0-1, x0-1); OOB mid = 0
    for (int t = p; t < 100; t += 8) {
        int my = t / 10, mx = t % 10;
        int gy = y0 - 1 + my, gx = x0 - 1 + mx;
        float a = bv1;
#pragma unroll
        for (int dy = 0; dy < 3; dy++)
#pragma unroll
            for (int dx = 0; dx < 3; dx++)
                a += w1[dy * 3 + dx] * s_in[(my + dy) * 12 + mx + dx][c];
        bool valid = (gy >= 0 && gy < Hh && gx >= 0 && gx < Ww);
        s_mid[t][c] = valid ? fmaxf(a, 0.f) : 0.f;
    }
    __syncthreads();

    // conv2 + bias -> 8x8 output
    for (int t = p; t < 64; t += 8) {
        int oy = t >> 3, ox = t & 7;
        float a = bv2;
#pragma unroll
        for (int dy = 0; dy < 3; dy++)
#pragma unroll
            for (int dx = 0; dx < 3; dx++)
                a += w2[dy * 3 + dx] * s_mid[(oy + dy) * 10 + ox + dx][c];
        out[((size_t)b * HW + (size_t)(y0 + oy) * Ww + (x0 + ox)) * Cc + ch] =
            __float2bfloat16(a);
    }
}

// ---------------- gather + residual + channel-BN stats (fused) -------------
// Requires g_acc zeroed before launch. Produces sum/sumsq of the UPDATED
// tokensT into g_acc for the subsequent channel-MLP BN.
__global__ void gather_kernel(const int* __restrict__ cellind,
                              const float* __restrict__ occ,
                              const float* __restrict__ scale,
                              const __nv_bfloat16* __restrict__ grid, int g) {
    int c = threadIdx.x;
    float sc = __ldg(&scale[c]);
    float s = 0.f, s2 = 0.f;
#pragma unroll
    for (int i = 0; i < 4; i++) {
        int p = blockIdx.x * 4 + i;
        int b = p >> 15;
        int n = p & (Nn - 1);
        int cell = __ldg(&cellind[(b * NG + g) * Nn + n]);
        float o  = __ldg(&occ[b * Nn + n]);
        float v  = __bfloat162float(grid[((size_t)b * HW + cell) * Cc + c]);
        float nv = g_tokensT[(size_t)p * Cc + c] + sc * o * v;
        g_tokensT[(size_t)p * Cc + c] = nv;
        s  += nv;
        s2 += nv * nv;
    }
    atomicAdd(&g_acc[c], s);
    atomicAdd(&g_acc[Cc + c], s2);
}

// ---------------- bf16 mma.sync GEMMs ----------------
// CTA tile 128(M) x 128(N), K-step 32. 8 warps (2x4), warp tile 64x32.
#define SMEM_LD 40   // halves per row (32 + 8 pad)

__device__ __forceinline__ void mma16816(float* c, const uint32_t* a, const uint32_t* b) {
    asm volatile(
        "mma.sync.aligned.m16n8k16.row.col.f32.bf16.bf16.f32 "
        "{%0,%1,%2,%3}, {%4,%5,%6,%7}, {%8,%9}, {%0,%1,%2,%3};"
        : "+f"(c[0]), "+f"(c[1]), "+f"(c[2]), "+f"(c[3])
        : "r"(a[0]), "r"(a[1]), "r"(a[2]), "r"(a[3]), "r"(b[0]), "r"(b[1]));
}

// GEMM1: H1[m,o] = relu( sum_c (tokensT[m,c]*bnA[c]+bnB[c]) * W1[o,c] + b1[o] ), bf16 out.
__global__ __launch_bounds__(256) void gemm1_kernel(const float* __restrict__ W,
                                                    const float* __restrict__ bias) {
    __shared__ __nv_bfloat16 As[128 * SMEM_LD];
    __shared__ __nv_bfloat16 Bs[128 * SMEM_LD];
    const int tid  = threadIdx.x;
    const int lane = tid & 31, warp = tid >> 5;
    const int wm = (warp >> 2) * 64, wn = (warp & 3) * 32;
    const int m0 = blockIdx.x * 128;
    const int n0 = blockIdx.y * 128;
    float acc[4][4][4];
#pragma unroll
    for (int i = 0; i < 4; i++)
#pragma unroll
        for (int j = 0; j < 4; j++)
#pragma unroll
            for (int k = 0; k < 4; k++) acc[i][j][k] = 0.f;

    const int kx    = tid & 7;    // 4-float k group
    const int rbase = tid >> 3;   // 0..31

    for (int k0 = 0; k0 < Cc; k0 += 32) {
#pragma unroll
        for (int r = 0; r < 4; r++) {
            int mloc = rbase + r * 32;
            int ccol = k0 + kx * 4;
            float4 v = *(const float4*)&g_tokensT[(size_t)(m0 + mloc) * Cc + ccol];
            float a0 = g_bnA[ccol], a1 = g_bnA[ccol + 1], a2 = g_bnA[ccol + 2], a3 = g_bnA[ccol + 3];
            float b0 = g_bnB[ccol], b1 = g_bnB[ccol + 1], b2 = g_bnB[ccol + 2], b3 = g_bnB[ccol + 3];
            union { uint2 u; __nv_bfloat162 h[2]; } pk;
            pk.h[0] = __floats2bfloat162_rn(v.x * a0 + b0, v.y * a1 + b1);
            pk.h[1] = __floats2bfloat162_rn(v.z * a2 + b2, v.w * a3 + b3);
            *(uint2*)&As[mloc * SMEM_LD + kx * 4] = pk.u;
        }
#pragma unroll
        for (int r = 0; r < 4; r++) {
            int oloc = rbase + r * 32;
            int ccol = k0 + kx * 4;
            float4 v = *(const float4*)&W[(size_t)(n0 + oloc) * Cc + ccol];
            union { uint2 u; __nv_bfloat162 h[2]; } pk;
            pk.h[0] = __floats2bfloat162_rn(v.x, v.y);
            pk.h[1] = __floats2bfloat162_rn(v.z, v.w);
            *(uint2*)&Bs[oloc * SMEM_LD + kx * 4] = pk.u;
        }
        __syncthreads();
#pragma unroll
        for (int ks = 0; ks < 32; ks += 16) {
            uint32_t af[4][4], bf[4][2];
#pragma unroll
            for (int mi = 0; mi < 4; mi++) {
                int row = wm + mi * 16 + (lane >> 2);
                int col = ks + (lane & 3) * 2;
                af[mi][0] = *(const uint32_t*)&As[row * SMEM_LD + col];
                af[mi][1] = *(const uint32_t*)&As[(row + 8) * SMEM_LD + col];
                af[mi][2] = *(const uint32_t*)&As[row * SMEM_LD + col + 8];
                af[mi][3] = *(const uint32_t*)&As[(row + 8) * SMEM_LD + col + 8];
            }
#pragma unroll
            for (int ni = 0; ni < 4; ni++) {
                int oc = wn + ni * 8 + (lane >> 2);
                int kr = ks + (lane & 3) * 2;
                bf[ni][0] = *(const uint32_t*)&Bs[oc * SMEM_LD + kr];
                bf[ni][1] = *(const uint32_t*)&Bs[oc * SMEM_LD + kr + 8];
            }
#pragma unroll
            for (int mi = 0; mi < 4; mi++)
#pragma unroll
                for (int ni = 0; ni < 4; ni++)
                    mma16816(acc[mi][ni], af[mi], bf[ni]);
        }
        __syncthreads();
    }
#pragma unroll
    for (int mi = 0; mi < 4; mi++)
#pragma unroll
        for (int ni = 0; ni < 4; ni++) {
            int row = m0 + wm + mi * 16 + (lane >> 2);
            int col = n0 + wn + ni * 8 + (lane & 3) * 2;
            float bb0 = __ldg(&bias[col]), bb1 = __ldg(&bias[col + 1]);
            float v0 = fmaxf(acc[mi][ni][0] + bb0, 0.f);
            float v1 = fmaxf(acc[mi][ni][1] + bb1, 0.f);
            float v2 = fmaxf(acc[mi][ni][2] + bb0, 0.f);
            float v3 = fmaxf(acc[mi][ni][3] + bb1, 0.f);
            *(__nv_bfloat162*)&g_H1[(size_t)row * Cc + col]       = __floats2bfloat162_rn(v0, v1);
            *(__nv_bfloat162*)&g_H1[(size_t)(row + 8) * Cc + col] = __floats2bfloat162_rn(v2, v3);
        }
}

// GEMM2: tokensT[m,o] += cm_scale[o] * ( sum_c H1[m,c]*W2[o,c] + b2[o] )
// Also accumulates sum/sumsq of the UPDATED tokensT per column into g_acc
// (spatial-BN stats for the NEXT layer). g_acc must be zeroed before launch.
__global__ __launch_bounds__(256) void gemm2_kernel(const float* __restrict__ W,
                                                    const float* __restrict__ bias,
                                                    const float* __restrict__ scale) {
    __shared__ __nv_bfloat16 As[128 * SMEM_LD];
    __shared__ __nv_bfloat16 Bs[128 * SMEM_LD];
    __shared__ float s_sum[128], s_sum2[128];
    const int tid  = threadIdx.x;
    const int lane = tid & 31, warp = tid >> 5;
    const int wm = (warp >> 2) * 64, wn = (warp & 3) * 32;
    const int m0 = blockIdx.x * 128;
    const int n0 = blockIdx.y * 128;
    if (tid < 128) { s_sum[tid] = 0.f; s_sum2[tid] = 0.f; }
    float acc[4][4][4];
#pragma unroll
    for (int i = 0; i < 4; i++)
#pragma unroll
        for (int j = 0; j < 4; j++)
#pragma unroll
            for (int k = 0; k < 4; k++) acc[i][j][k] = 0.f;

    const int kx  = tid & 7;
    const int rb  = tid >> 3;   // 0..31 (B load)
    const int kx2 = tid & 3;
    const int rb2 = tid >> 2;   // 0..63 (A load)

    for (int k0 = 0; k0 < Cc; k0 += 32) {
#pragma unroll
        for (int r = 0; r < 2; r++) {
            int mloc = rb2 + r * 64;
            int ccol = k0 + kx2 * 8;
            uint4 v = *(const uint4*)&g_H1[(size_t)(m0 + mloc) * Cc + ccol];
            *(uint4*)&As[mloc * SMEM_LD + kx2 * 8] = v;
        }
#pragma unroll
        for (int r = 0; r < 4; r++) {
            int oloc = rb + r * 32;
            int ccol = k0 + kx * 4;
            float4 v = *(const float4*)&W[(size_t)(n0 + oloc) * Cc + ccol];
            union { uint2 u; __nv_bfloat162 h[2]; } pk;
            pk.h[0] = __floats2bfloat162_rn(v.x, v.y);
            pk.h[1] = __floats2bfloat162_rn(v.z, v.w);
            *(uint2*)&Bs[oloc * SMEM_LD + kx * 4] = pk.u;
        }
        __syncthreads();
#pragma unroll
        for (int ks = 0; ks < 32; ks += 16) {
            uint32_t af[4][4], bf[4][2];
#pragma unroll
            for (int mi = 0; mi < 4; mi++) {
                int row = wm + mi * 16 + (lane >> 2);
                int col = ks + (lane & 3) * 2;
                af[mi][0] = *(const uint32_t*)&As[row * SMEM_LD + col];
                af[mi][1] = *(const uint32_t*)&As[(row + 8) * SMEM_LD + col];
                af[mi][2] = *(const uint32_t*)&As[row * SMEM_LD + col + 8];
                af[mi][3] = *(const uint32_t*)&As[(row + 8) * SMEM_LD + col + 8];
            }
#pragma unroll
            for (int ni = 0; ni < 4; ni++) {
                int oc = wn + ni * 8 + (lane >> 2);
                int kr = ks + (lane & 3) * 2;
                bf[ni][0] = *(const uint32_t*)&Bs[oc * SMEM_LD + kr];
                bf[ni][1] = *(const uint32_t*)&Bs[oc * SMEM_LD + kr + 8];
            }
#pragma unroll
            for (int mi = 0; mi < 4; mi++)
#pragma unroll
                for (int ni = 0; ni < 4; ni++)
                    mma16816(acc[mi][ni], af[mi], bf[ni]);
        }
        __syncthreads();
    }
#pragma unroll
    for (int ni = 0; ni < 4; ni++) {
        int coll = wn + ni * 8 + (lane & 3) * 2;   // CTA-local column
        int col  = n0 + coll;
        float bb0 = __ldg(&bias[col]),  bb1 = __ldg(&bias[col + 1]);
        float s0  = __ldg(&scale[col]), s1  = __ldg(&scale[col + 1]);
        float cs0 = 0.f, cq0 = 0.f, cs1 = 0.f, cq1 = 0.f;
#pragma unroll
        for (int mi = 0; mi < 4; mi++) {
            int row = m0 + wm + mi * 16 + (lane >> 2);
            {
                float2* p = (float2*)&g_tokensT[(size_t)row * Cc + col];
                float2 t = *p;
                t.x += s0 * (acc[mi][ni][0] + bb0);
                t.y += s1 * (acc[mi][ni][1] + bb1);
                *p = t;
                cs0 += t.x; cq0 += t.x * t.x;
                cs1 += t.y; cq1 += t.y * t.y;
            }
            {
                float2* p = (float2*)&g_tokensT[(size_t)(row + 8) * Cc + col];
                float2 t = *p;
                t.x += s0 * (acc[mi][ni][2] + bb0);
                t.y += s1 * (acc[mi][ni][3] + bb1);
                *p = t;
                cs0 += t.x; cq0 += t.x * t.x;
                cs1 += t.y; cq1 += t.y * t.y;
            }
        }
        atomicAdd(&s_sum [coll],     cs0);
        atomicAdd(&s_sum2[coll],     cq0);
        atomicAdd(&s_sum [coll + 1], cs1);
        atomicAdd(&s_sum2[coll + 1], cq1);
    }
    __syncthreads();
    if (tid < 128) {
        atomicAdd(&g_acc[n0 + tid],      s_sum [tid]);
        atomicAdd(&g_acc[Cc + n0 + tid], s_sum2[tid]);
    }
}

// ---------------------------------------------------------------------------
extern "C" void kernel_launch(void* const* d_in, const int* in_sizes, int n_in,
                              void* d_out, int out_size) {
    const float* tokens   = (const float*)d_in[0];
    const int*   cell_ind = (const int*)  d_in[1];
    const float* occ      = (const float*)d_in[2];
    const float* cm_gamma = (const float*)d_in[3];
    const float* cm_beta  = (const float*)d_in[4];
    const float* cm_w1    = (const float*)d_in[5];
    const float* cm_b1    = (const float*)d_in[6];
    const float* cm_w2    = (const float*)d_in[7];
    const float* cm_b2    = (const float*)d_in[8];
    const float* cm_scale = (const float*)d_in[9];
    const float* sm_gamma = (const float*)d_in[10];
    const float* sm_beta  = (const float*)d_in[11];
    const float* sm_k1    = (const float*)d_in[12];
    const float* sm_b1    = (const float*)d_in[13];
    const float* sm_k2    = (const float*)d_in[14];
    const float* sm_b2    = (const float*)d_in[15];
    const float* sm_scale = (const float*)d_in[16];

    __nv_bfloat16 *gridPtr, *grid2Ptr;
    float *countsPtr, *accPtr;
    cudaGetSymbolAddress((void**)&gridPtr,   g_grid);
    cudaGetSymbolAddress((void**)&grid2Ptr,  g_grid2);
    cudaGetSymbolAddress((void**)&countsPtr, g_counts);
    cudaGetSymbolAddress((void**)&accPtr,    g_acc);

    // tokens -> [B*N, C]
    transpose_in_kernel<<<dim3(Nn / 32, Cc / 32, Bn), dim3(32, 8)>>>(tokens);

    // cell counts (shared across layers)
    {
        int n4 = (Bn * NG * HW) / 4;
        zero4_kernel<<<(n4 + 255) / 256, 256>>>((float4*)countsPtr, n4);
        hist_kernel<<<(Bn * NG * Nn) / 256, 256>>>(cell_ind, occ);
    }

    // layer-0 spatial-BN stats (standalone pass; later layers get them from
    // the previous gemm2 epilogue)
    zero4_kernel<<<1, 256>>>((float4*)accPtr, (2 * Cc) / 4);
    bn_accum_kernel<<<ROWS / 256, 256>>>();

    // bf16 grid: bytes = Bn*HW*Cc*2; float4 elements = bytes/16
    const int gridN4 = (int)(((size_t)Bn * HW * Cc * 2) / 16);
    for (int d = 0; d < Dd; d++) {
        int g = d % NG;
        // ---- spatial branch ----
        bn_final_kernel<<<1, Cc>>>(sm_gamma + d * Cc, sm_beta + d * Cc);

        zero4_kernel<<<(gridN4 + 255) / 256, 256>>>((float4*)gridPtr, gridN4);
        scatter_kernel<<<ROWS / 4, 128>>>(cell_ind, occ, g);
        conv_fused_kernel<<<dim3(Ww / 8, Hh / 8, Bn * (Cc / CT)), 256>>>(
            gridPtr, grid2Ptr,
            sm_k1 + (size_t)d * Cc * 9, sm_b1 + d * Cc,
            sm_k2 + (size_t)d * Cc * 9, sm_b2 + d * Cc);

        // zero acc BEFORE gather; gather fuses channel-BN stat accumulation
        zero4_kernel<<<1, 256>>>((float4*)accPtr, (2 * Cc) / 4);
        gather_kernel<<<ROWS / 4, Cc>>>(cell_ind, occ, sm_scale + d * Cc, grid2Ptr, g);

        // ---- channel MLP ----
        bn_final_kernel<<<1, Cc>>>(cm_gamma + d * Cc, cm_beta + d * Cc);

        gemm1_kernel<<<dim3(ROWS / 128, Cc / 128), 256>>>(cm_w1 + (size_t)d * Cc * Cc,
                                                          cm_b1 + d * Cc);
        // zero acc BEFORE gemm2; gemm2 fuses next layer's spatial-BN stats
        zero4_kernel<<<1, 256>>>((float4*)accPtr, (2 * Cc) / 4);
        gemm2_kernel<<<dim3(ROWS / 128, Cc / 128), 256>>>(cm_w2 + (size_t)d * Cc * Cc,
                                                          cm_b2 + d * Cc,
                                                          cm_scale + d * Cc);
    }

    // tokensT -> output [B,C,N]
    transpose_out_kernel<<<dim3(Nn / 32, Cc / 32, Bn), dim3(32, 8)>>>((float*)d_out);
}